// round 6
// baseline (speedup 1.0000x reference)
#include <cuda_runtime.h>
#include <cstdint>
#include <cstddef>

// ---------------------------------------------------------------------------
// DynamicGraphBuilder: per (b,t) item: 19x19 cosine similarity -> /0.1 ->
// softmax -> top-3 keep -> threshold 1e-4 -> 0.5*(A+A^T).
// One warp per item. F staged in SMEM with XOR chunk swizzle; Gram computed
// with 4x4 register tiles over the upper triangle, 2-way d-split per tile,
// packed fma.rn.f32x2. Epilogue lane-per-row, coalesced flat output store.
// ---------------------------------------------------------------------------

namespace {

constexpr int kB = 32;
constexpr int kN = 19;
constexpr int kT = 2048;
constexpr int kD = 128;
constexpr int kItems = kB * kT;            // 65536
constexpr int kWarpsPerCta = 4;
constexpr int kThreads = kWarpsPerCta * 32;
constexpr int kGrid = kItems / kWarpsPerCta;

constexpr float kInvTemp = 10.0f;          // 1 / 0.1
constexpr float kThresh = 1e-4f;

// Per-warp SMEM layout (float words):
//   F   : 20 rows x 128 (row 19 = zero pad), XOR-swizzled in float4 chunks
//   G   : 20 x stride 21 (gram, later reused as sparse matrix S)
//   rinv: 19 (+pad)
constexpr int kFWords = 20 * 128;                 // 2560
constexpr int kGOff = kFWords;                    // 2560
constexpr int kGS = 21;
constexpr int kRinvOff = kGOff + 20 * kGS;        // 2980
constexpr int kWarpWords = 3008;                  // 12032 B / warp
// 4 warps -> 48128 B static shared (within 48KB default)

__device__ __forceinline__ int swz(int n) { return (n + (n >> 2)) & 7; }

__device__ __forceinline__ unsigned long long ffma2(unsigned long long a,
                                                    unsigned long long b,
                                                    unsigned long long c) {
    unsigned long long d;
    asm("fma.rn.f32x2 %0, %1, %2, %3;" : "=l"(d) : "l"(a), "l"(b), "l"(c));
    return d;
}

__device__ __forceinline__ float2 unpack2(unsigned long long v) {
    float2 r;
    asm("mov.b64 {%0, %1}, %2;" : "=f"(r.x), "=f"(r.y) : "l"(v));
    return r;
}

__global__ void __launch_bounds__(kThreads, 4)
dgb_kernel(const float* __restrict__ feat, float* __restrict__ out) {
    __shared__ float sm[kWarpsPerCta * kWarpWords];

    const int lane = threadIdx.x & 31;
    const int w = threadIdx.x >> 5;
    const int item = blockIdx.x * kWarpsPerCta + w;     // < 65536
    const int b = item >> 11;                           // / kT
    const int t = item & (kT - 1);

    float* __restrict__ Fw = sm + w * kWarpWords;       // F region
    float* __restrict__ G = Fw + kGOff;                 // gram / sparse
    float* __restrict__ Rv = Fw + kRinvOff;             // rinv

    // ---- zero pad row 19 ----
    {
        float4 z = make_float4(0.f, 0.f, 0.f, 0.f);
        int idx = 19 * 128 + ((lane ^ swz(19)) << 2);
        *reinterpret_cast<float4*>(Fw + idx) = z;
    }

    // ---- stage 19 rows GMEM -> SMEM (cp.async 16B, swizzled dst) ----
    {
        unsigned fb = (unsigned)__cvta_generic_to_shared(Fw);
        const float* src0 =
            feat + (((size_t)b * kN) * kT + (size_t)t) * kD + lane * 4;
#pragma unroll
        for (int n = 0; n < kN; ++n) {
            unsigned dst = fb + (unsigned)((n * 128 + ((lane ^ swz(n)) << 2)) * 4);
            const float* src = src0 + (size_t)n * (kT * kD);
            asm volatile("cp.async.cg.shared.global [%0], [%1], 16;"
                         :: "r"(dst), "l"(src) : "memory");
        }
        asm volatile("cp.async.commit_group;" ::: "memory");
        asm volatile("cp.async.wait_group 0;" ::: "memory");
    }
    __syncwarp();

    // ---- tile map: 15 upper-tri 4x4 tiles over a 20x20 grid, 2 d-halves ----
    // lane s: tile = min(s>>1, 14), half = s&1. Lanes 30,31 duplicate tile 14.
    const int s = lane;
    int tile = s >> 1;
    if (tile > 14) tile = 14;
    const int h = s & 1;
    int a, q;
    if (tile < 5)       { a = 0; q = tile; }
    else if (tile < 9)  { a = 1; q = tile - 4; }
    else if (tile < 12) { a = 2; q = tile - 7; }
    else if (tile < 14) { a = 3; q = tile - 9; }
    else                { a = 4; q = 4; }

    // Row/col base pointers (include the 2h sub-offset) and swizzle keys.
    const float* pa[4];
    const float* pb[4];
    int sa[4], sb_[4];
#pragma unroll
    for (int r = 0; r < 4; ++r) {
        int n = 4 * a + r;
        pa[r] = Fw + n * 128 + 2 * h;
        sa[r] = swz(n);
        int m = 4 * q + r;
        pb[r] = Fw + m * 128 + 2 * h;
        sb_[r] = swz(m);
    }

    unsigned long long acc[4][4];
#pragma unroll
    for (int r = 0; r < 4; ++r)
#pragma unroll
        for (int c = 0; c < 4; ++c) acc[r][c] = 0ull;

    // Each lane covers d in { 4*it + 2h, 4*it + 2h + 1 } for it = 0..31.
#pragma unroll
    for (int it = 0; it < 32; ++it) {
        unsigned long long av[4], bv[4];
#pragma unroll
        for (int r = 0; r < 4; ++r)
            av[r] = *reinterpret_cast<const unsigned long long*>(
                pa[r] + ((it ^ sa[r]) << 2));
#pragma unroll
        for (int c = 0; c < 4; ++c)
            bv[c] = *reinterpret_cast<const unsigned long long*>(
                pb[c] + ((it ^ sb_[c]) << 2));
#pragma unroll
        for (int r = 0; r < 4; ++r)
#pragma unroll
            for (int c = 0; c < 4; ++c)
                acc[r][c] = ffma2(av[r], bv[c], acc[r][c]);
    }

    // ---- reduce halves and scatter gram (+ symmetric mirror) ----
#pragma unroll
    for (int r = 0; r < 4; ++r) {
#pragma unroll
        for (int c = 0; c < 4; ++c) {
            float2 p = unpack2(acc[r][c]);
            float v = p.x + p.y;
            v += __shfl_xor_sync(0xffffffffu, v, 1);
            if (h == 0 && s < 30) {
                int R = 4 * a + r, C = 4 * q + c;
                G[R * kGS + C] = v;
                G[C * kGS + R] = v;
            }
        }
    }
    __syncwarp();

    // ---- epilogue: lane i owns row i ----
    const int i = lane;
    if (i < kN) {
        float g[kN];
#pragma unroll
        for (int j = 0; j < kN; ++j) g[j] = G[i * kGS + j];

        float rinv_i = rsqrtf(fmaxf(g[i], 1e-24f));
        Rv[i] = rinv_i;
    }
    __syncwarp();

    if (i < kN) {
        float g[kN];
#pragma unroll
        for (int j = 0; j < kN; ++j) g[j] = G[i * kGS + j];
        float rinv_i = Rv[i];

        // scaled cosine: c = g * rinv_i * rinv_j * 10
        float m = -1e30f;
#pragma unroll
        for (int j = 0; j < kN; ++j) {
            g[j] = g[j] * (rinv_i * kInvTemp) * Rv[j];
            m = fmaxf(m, g[j]);
        }
        float sum = 0.f;
#pragma unroll
        for (int j = 0; j < kN; ++j) {
            g[j] = __expf(g[j] - m);
            sum += g[j];
        }
        float inv = 1.0f / sum;

        // top-3 tracking
        float t1 = -1e30f, t2 = -1e30f, t3 = -1e30f;
#pragma unroll
        for (int j = 0; j < kN; ++j) {
            float v = g[j] * inv;
            g[j] = v;
            if (v > t1)      { t3 = t2; t2 = t1; t1 = v; }
            else if (v > t2) { t3 = t2; t2 = v; }
            else if (v > t3) { t3 = v; }
        }

        // sparsify + threshold; write sparse row back into G (reuse as S)
#pragma unroll
        for (int j = 0; j < kN; ++j) {
            float v = g[j];
            float kept = (v >= t3 && v > kThresh) ? v : 0.0f;
            G[i * kGS + j] = kept;
        }
    }
    __syncwarp();

    // ---- symmetrize + coalesced store: 361 floats per item ----
    {
        float* dst = out + (size_t)item * (kN * kN);
#pragma unroll
        for (int k = lane; k < kN * kN; k += 32) {
            int ii = k / kN;
            int jj = k - ii * kN;
            float v = 0.5f * (G[ii * kGS + jj] + G[jj * kGS + ii]);
            dst[k] = v;
        }
    }
}

}  // namespace

extern "C" void kernel_launch(void* const* d_in, const int* in_sizes, int n_in,
                              void* d_out, int out_size) {
    (void)in_sizes; (void)n_in; (void)out_size;
    const float* feat = (const float*)d_in[0];
    float* out = (float*)d_out;
    dgb_kernel<<<kGrid, kThreads>>>(feat, out);
}

// round 8
// speedup vs baseline: 1.0548x; 1.0548x over previous
#include <cuda_runtime.h>
#include <cstdint>
#include <cstddef>

// ---------------------------------------------------------------------------
// DynamicGraphBuilder: per (b,t) item: 19x19 cosine similarity -> /0.1 ->
// softmax -> top-3 keep -> threshold 1e-4 -> 0.5*(A+A^T).
// One warp per item. F staged in SMEM with a group-level XOR granule swizzle;
// Gram via 15 upper-tri 4x4 register tiles, d split by granule parity,
// LDS.128 operand loads feeding packed fma.rn.f32x2. 5 CTAs/SM (45.3KB).
// ---------------------------------------------------------------------------

namespace {

constexpr int kN = 19;
constexpr int kT = 2048;
constexpr int kD = 128;
constexpr int kItems = 32 * kT;            // 65536
constexpr int kWarpsPerCta = 4;
constexpr int kThreads = kWarpsPerCta * 32;
constexpr int kGrid = kItems / kWarpsPerCta;

constexpr float kInvTemp = 10.0f;          // 1 / 0.1
constexpr float kThresh = 1e-4f;

// Per-warp SMEM layout (float words):
//   F : 19 rows x 128, granule(16B)-swizzled:  granule stored at (c ^ key(n))
//       with key(n) = (5*(n>>2)) & 7  (shared by all 4 rows of a group)
//   G : 19 x stride 21 (gram; later reused as sparse matrix)
constexpr int kFWords = 19 * 128;                 // 2432
constexpr int kGOff = kFWords;                    // 2432
constexpr int kGS = 21;
constexpr int kWarpWords = 2832;                  // 11328 B / warp
// 4 warps -> 45312 B static shared -> 5 CTAs / SM

__device__ __forceinline__ int gkey(int grp) { return (5 * grp) & 7; }

__device__ __forceinline__ unsigned long long ffma2(unsigned long long a,
                                                    unsigned long long b,
                                                    unsigned long long c) {
    unsigned long long d;
    asm("fma.rn.f32x2 %0, %1, %2, %3;" : "=l"(d) : "l"(a), "l"(b), "l"(c));
    return d;
}

__device__ __forceinline__ float2 unpack2(unsigned long long v) {
    float2 r;
    asm("mov.b64 {%0, %1}, %2;" : "=f"(r.x), "=f"(r.y) : "l"(v));
    return r;
}

__device__ __forceinline__ void lds128(unsigned addr,
                                       unsigned long long& lo,
                                       unsigned long long& hi) {
    asm volatile("ld.shared.v2.u64 {%0, %1}, [%2];"
                 : "=l"(lo), "=l"(hi) : "r"(addr));
}

__global__ void __launch_bounds__(kThreads, 5)
dgb_kernel(const float* __restrict__ feat, float* __restrict__ out) {
    __shared__ float sm[kWarpsPerCta * kWarpWords];

    const int lane = threadIdx.x & 31;
    const int w = threadIdx.x >> 5;
    const int item = blockIdx.x * kWarpsPerCta + w;     // < 65536
    const int b = item >> 11;                           // / kT
    const int t = item & (kT - 1);

    float* __restrict__ Fw = sm + w * kWarpWords;
    float* __restrict__ G = Fw + kGOff;
    const unsigned fb = (unsigned)__cvta_generic_to_shared(Fw);

    // ---- stage 19 rows GMEM -> SMEM (cp.async 16B, granule swizzle) ----
    {
        const float* src0 =
            feat + (((size_t)b * kN) * kT + (size_t)t) * kD + lane * 4;
#pragma unroll
        for (int n = 0; n < kN; ++n) {
            unsigned dst = fb + (unsigned)(n * 512 + ((lane ^ gkey(n >> 2)) << 4));
            const float* src = src0 + (size_t)n * (kT * kD);
            asm volatile("cp.async.cg.shared.global [%0], [%1], 16;"
                         :: "r"(dst), "l"(src) : "memory");
        }
        asm volatile("cp.async.commit_group;" ::: "memory");
        asm volatile("cp.async.wait_group 0;" ::: "memory");
    }
    __syncwarp();

    // ---- tile map: 15 upper-tri 4x4 tiles over a padded 20x20 grid ----
    // lane s: tile = min(s>>1, 14), h = s&1 (granule parity). Lanes 30,31
    // duplicate tile 14.
    const int s = lane;
    int tile = s >> 1;
    if (tile > 14) tile = 14;
    const int h = s & 1;
    int a, q;
    if (tile < 5)       { a = 0; q = tile; }
    else if (tile < 9)  { a = 1; q = tile - 4; }
    else if (tile < 12) { a = 2; q = tile - 7; }
    else if (tile < 14) { a = 3; q = tile - 9; }
    else                { a = 4; q = 4; }

    const int fa = gkey(a);
    const int fq = gkey(q);

    // Row base addresses (bytes, shared space); rows >= 19 clamp to 18
    // (their products are predicated out of the gram scatter).
    unsigned baseA[4], baseB[4];
#pragma unroll
    for (int r = 0; r < 4; ++r) {
        int rn = 4 * a + r; if (rn > 18) rn = 18;
        int cn = 4 * q + r; if (cn > 18) cn = 18;
        baseA[r] = fb + (unsigned)(rn * 512);
        baseB[r] = fb + (unsigned)(cn * 512);
    }

    unsigned long long acc[4][4];
#pragma unroll
    for (int r = 0; r < 4; ++r)
#pragma unroll
        for (int c = 0; c < 4; ++c) acc[r][c] = 0ull;

    // Each lane handles granules g = 2*it + h (16 granules x 4 d = 64 d vals).
#pragma unroll
    for (int it = 0; it < 16; ++it) {
        const int g = 2 * it + h;
        const unsigned offA = (unsigned)((g ^ fa) << 4);
        const unsigned offB = (unsigned)((g ^ fq) << 4);
        unsigned long long alo[4], ahi[4], blo[4], bhi[4];
#pragma unroll
        for (int r = 0; r < 4; ++r) lds128(baseA[r] + offA, alo[r], ahi[r]);
#pragma unroll
        for (int c = 0; c < 4; ++c) lds128(baseB[c] + offB, blo[c], bhi[c]);
#pragma unroll
        for (int r = 0; r < 4; ++r)
#pragma unroll
            for (int c = 0; c < 4; ++c) {
                acc[r][c] = ffma2(alo[r], blo[c], acc[r][c]);
                acc[r][c] = ffma2(ahi[r], bhi[c], acc[r][c]);
            }
    }

    // ---- reduce halves and scatter gram (+ symmetric mirror) ----
#pragma unroll
    for (int r = 0; r < 4; ++r) {
#pragma unroll
        for (int c = 0; c < 4; ++c) {
            float2 p = unpack2(acc[r][c]);
            float v = p.x + p.y;
            v += __shfl_xor_sync(0xffffffffu, v, 1);
            const int R = 4 * a + r, C = 4 * q + c;
            if (h == 0 && s < 30 && R < kN && C < kN) {
                G[R * kGS + C] = v;
                G[C * kGS + R] = v;
            }
        }
    }
    __syncwarp();

    // ---- epilogue: lane i owns row i (unguarded; lanes >=19 clamp) ----
    {
        const int ir = (lane < kN) ? lane : (kN - 1);
        float g[kN];
#pragma unroll
        for (int j = 0; j < kN; ++j) g[j] = G[ir * kGS + j];

        const float rinv = rsqrtf(fmaxf(g[ir], 1e-24f));
        const float ri10 = rinv * kInvTemp;

        float m = -1e30f;
#pragma unroll
        for (int j = 0; j < kN; ++j) {
            float rj = __shfl_sync(0xffffffffu, rinv, j);
            g[j] = g[j] * ri10 * rj;
            m = fmaxf(m, g[j]);
        }
        float sum = 0.f;
#pragma unroll
        for (int j = 0; j < kN; ++j) {
            g[j] = __expf(g[j] - m);
            sum += g[j];
        }
        const float inv = 1.0f / sum;

        float t1 = -1e30f, t2 = -1e30f, t3 = -1e30f;
#pragma unroll
        for (int j = 0; j < kN; ++j) {
            float v = g[j] * inv;
            g[j] = v;
            if (v > t1)      { t3 = t2; t2 = t1; t1 = v; }
            else if (v > t2) { t3 = t2; t2 = v; }
            else if (v > t3) { t3 = v; }
        }

        if (lane < kN) {
#pragma unroll
            for (int j = 0; j < kN; ++j) {
                float v = g[j];
                G[lane * kGS + j] = (v >= t3 && v > kThresh) ? v : 0.0f;
            }
        }
    }
    __syncwarp();

    // ---- symmetrize + coalesced store: 361 floats per item ----
    {
        float* dst = out + (size_t)item * (kN * kN);
#pragma unroll
        for (int k = lane; k < kN * kN; k += 32) {
            int ii = k / kN;
            int jj = k - ii * kN;
            dst[k] = 0.5f * (G[ii * kGS + jj] + G[jj * kGS + ii]);
        }
    }
}

}  // namespace

extern "C" void kernel_launch(void* const* d_in, const int* in_sizes, int n_in,
                              void* d_out, int out_size) {
    (void)in_sizes; (void)n_in; (void)out_size;
    const float* feat = (const float*)d_in[0];
    float* out = (float*)d_out;
    dgb_kernel<<<kGrid, kThreads>>>(feat, out);
}